// round 3
// baseline (speedup 1.0000x reference)
#include <cuda_runtime.h>
#include <math.h>

// ---------------------------------------------------------------------------
// ConvLSTM stack: 4x (ConvLSTM2D(valid input conv, same recurrent conv,
// hard_sigmoid gates i,f,c,o, tanh) + MaxPool(2,2,'SAME')) -> Dense(50) -> softmax
// B=32, T=24. All fp32.
// R2: weight-stationary register tiling (PX pixels/thread) to fix LDS-bound mix.
// ---------------------------------------------------------------------------

static constexpr int Bv = 32;
static constexpr int Tv = 24;

__device__ float g_hs1[(size_t)Bv*Tv*126*126*4];
__device__ float g_c1 [(size_t)Bv*126*126*4];
__device__ float g_p1 [(size_t)Bv*Tv*63*63*4];
__device__ float g_hs2[(size_t)Bv*Tv*61*61*8];
__device__ float g_c2 [(size_t)Bv*61*61*8];
__device__ float g_p2 [(size_t)Bv*Tv*31*31*8];
__device__ float g_hs3[(size_t)Bv*Tv*29*29*12];
__device__ float g_c3 [(size_t)Bv*29*29*12];
__device__ float g_p3 [(size_t)Bv*Tv*15*15*12];
__device__ float g_hs4[(size_t)Bv*Tv*13*13*16];
__device__ float g_c4 [(size_t)Bv*13*13*16];
__device__ float g_p4 [(size_t)Bv*Tv*7*7*16];
__device__ float g_logits[Bv*50];

__device__ __forceinline__ float hsig(float x) { return __saturatef(0.2f * x + 0.5f); }

// Weight-stationary FMA: load G4 weights once from shared, apply to PX pixels.
template<int G4, int PX>
__device__ __forceinline__ void wfma(float (&acc)[PX][G4], const float* __restrict__ v,
                                     const float* __restrict__ wsh) {
    float w[G4];
    #pragma unroll
    for (int q = 0; q < G4; q += 4) {
        float4 t4 = *reinterpret_cast<const float4*>(wsh + q);
        w[q] = t4.x; w[q+1] = t4.y; w[q+2] = t4.z; w[q+3] = t4.w;
    }
    #pragma unroll
    for (int p = 0; p < PX; p++) {
        float vv = v[p];
        #pragma unroll
        for (int k = 0; k < G4; k++) acc[p][k] += vv * w[k];
    }
}

// One ConvLSTM timestep: fused input conv (VALID) + recurrent conv (SAME) + gates.
// Thread = PX consecutive output pixels along x, FT feature channels (all 4 gates).
// grid.y = feature-channel group (warp-uniform weight addresses in shared).
template<int CIN, int F, int FT, int HIN, int WIN, int PX>
__global__ void __launch_bounds__(128)
lstm_step(const float* __restrict__ in_seq,   // (B,T,HIN,WIN,CIN)
          const float* __restrict__ Wx,       // (3,3,CIN,4F)
          const float* __restrict__ Wh,       // (3,3,F,4F)
          const float* __restrict__ bias,     // (4F,)
          float* __restrict__ hs,             // (B,T,HO,WO,F)
          float* __restrict__ c_buf,          // (B,HO,WO,F)
          int t)
{
    constexpr int HO = HIN - 2, WO = WIN - 2;
    constexpr int C4 = 4 * F;
    constexpr int G4 = 4 * FT;
    constexpr int NTX = (WO + PX - 1) / PX;
    constexpr int WXs = 9 * CIN * G4;
    constexpr int WHs = 9 * F * G4;
    __shared__ __align__(16) float sw[WXs + WHs];

    const int f0 = blockIdx.y * FT;

    // Gate-column-sliced weights into shared: layout [(ky*3+kx)*C + ci][G4]
    for (int i = threadIdx.x; i < WXs; i += blockDim.x) {
        int col = i % G4, rc = i / G4;
        int g = col / FT, j = col % FT;
        sw[i] = Wx[rc * C4 + g * F + f0 + j];
    }
    for (int i = threadIdx.x; i < WHs; i += blockDim.x) {
        int col = i % G4, rc = i / G4;
        int g = col / FT, j = col % FT;
        sw[WXs + i] = Wh[rc * C4 + g * F + f0 + j];
    }
    __syncthreads();

    const int NT = Bv * HO * NTX;
    int tid = blockIdx.x * blockDim.x + threadIdx.x;
    if (tid >= NT) return;
    int b = tid / (HO * NTX);
    int r = tid % (HO * NTX);
    int y = r / NTX;
    int x0 = (r % NTX) * PX;

    float acc[PX][G4];
    #pragma unroll
    for (int g = 0; g < 4; g++)
        #pragma unroll
        for (int j = 0; j < FT; j++) {
            float bv = __ldg(&bias[g * F + f0 + j]);
            #pragma unroll
            for (int p = 0; p < PX; p++) acc[p][g * FT + j] = bv;
        }

    // ---- Input conv (VALID, cross-correlation) ----
    const float* xin = in_seq + ((size_t)(b * Tv + t)) * HIN * WIN * CIN;
    #pragma unroll
    for (int ky = 0; ky < 3; ky++) {
        const float* row = xin + (size_t)(y + ky) * WIN * CIN;
        #pragma unroll
        for (int ci = 0; ci < CIN; ci++) {
            float v[PX + 2];
            #pragma unroll
            for (int u = 0; u < PX + 2; u++) {
                int xx = x0 + u;
                if (xx > WIN - 1) xx = WIN - 1;     // clamp (masked at write)
                v[u] = __ldg(row + xx * CIN + ci);
            }
            #pragma unroll
            for (int kx = 0; kx < 3; kx++)
                wfma<G4, PX>(acc, v + kx, sw + ((ky * 3 + kx) * CIN + ci) * G4);
        }
    }

    // ---- Recurrent conv (SAME, zero pad); h_{t-1} = hs slice t-1 ----
    if (t > 0) {
        const float* hp = hs + ((size_t)(b * Tv + (t - 1))) * HO * WO * F;
        #pragma unroll
        for (int ky = 0; ky < 3; ky++) {
            int yy = y + ky - 1;
            if (yy < 0 || yy >= HO) continue;
            const float* row = hp + (size_t)yy * WO * F;
            #pragma unroll
            for (int ci = 0; ci < F; ci++) {
                float v[PX + 2];
                #pragma unroll
                for (int u = 0; u < PX + 2; u++) {
                    int xx = x0 + u - 1;
                    v[u] = (xx >= 0 && xx < WO) ? __ldg(row + xx * F + ci) : 0.0f;
                }
                #pragma unroll
                for (int kx = 0; kx < 3; kx++)
                    wfma<G4, PX>(acc, v + kx, sw + WXs + ((ky * 3 + kx) * F + ci) * G4);
            }
        }
    }

    // ---- Gates (order i, f, c, o) ----
    #pragma unroll
    for (int p = 0; p < PX; p++) {
        int xp = x0 + p;
        if (xp >= WO) break;
        size_t pix = (size_t)b * HO * WO + (size_t)y * WO + xp;
        float* cp = c_buf + pix * F + f0;
        float* ho = hs + ((size_t)(b * Tv + t)) * HO * WO * F
                       + ((size_t)y * WO + xp) * F + f0;
        #pragma unroll
        for (int j = 0; j < FT; j++) {
            float iv = acc[p][j];
            float fv = acc[p][FT + j];
            float cv = acc[p][2 * FT + j];
            float ov = acc[p][3 * FT + j];
            float cold = (t > 0) ? cp[j] : 0.0f;
            float cn = hsig(fv) * cold + hsig(iv) * tanhf(cv);
            cp[j] = cn;
            ho[j] = hsig(ov) * tanhf(cn);
        }
    }
}

// MaxPool (1,2,2) stride (1,2,2), padding SAME, over (B*T, H, W, C)
__global__ void maxpool_k(const float* __restrict__ in, float* __restrict__ out,
                          int H, int W, int C, int HO, int WO, int total)
{
    int idx = blockIdx.x * blockDim.x + threadIdx.x;
    if (idx >= total) return;
    int c = idx % C; int r = idx / C;
    int ox = r % WO; r /= WO;
    int oy = r % HO; r /= HO;                 // r = bt
    const float* base = in + (size_t)r * H * W * C;
    int iy = 2 * oy, ix = 2 * ox;
    float m = base[((size_t)iy * W + ix) * C + c];
    if (ix + 1 < W) m = fmaxf(m, base[((size_t)iy * W + ix + 1) * C + c]);
    if (iy + 1 < H) {
        m = fmaxf(m, base[((size_t)(iy + 1) * W + ix) * C + c]);
        if (ix + 1 < W) m = fmaxf(m, base[((size_t)(iy + 1) * W + ix + 1) * C + c]);
    }
    out[idx] = m;
}

// Dense: logits[b,k] = sum_j xf[b,j]*Wd[j,k] + bd[k];   FLAT=18816, NC=50
__global__ void dense_k(const float* __restrict__ xf, const float* __restrict__ Wd,
                        const float* __restrict__ bd, float* __restrict__ logits)
{
    const int FLAT = 18816, NC = 50;
    int b = blockIdx.x, k = blockIdx.y;
    float s = 0.0f;
    for (int j = threadIdx.x; j < FLAT; j += blockDim.x)
        s += xf[(size_t)b * FLAT + j] * __ldg(&Wd[(size_t)j * NC + k]);
    __shared__ float red[128];
    red[threadIdx.x] = s;
    __syncthreads();
    for (int off = 64; off > 0; off >>= 1) {
        if (threadIdx.x < off) red[threadIdx.x] += red[threadIdx.x + off];
        __syncthreads();
    }
    if (threadIdx.x == 0) logits[b * NC + k] = red[0] + __ldg(&bd[k]);
}

__global__ void softmax_k(const float* __restrict__ logits, float* __restrict__ out)
{
    const int NC = 50;
    int b = blockIdx.x, t = threadIdx.x;
    __shared__ float s[64];
    float v = (t < NC) ? logits[b * NC + t] : -INFINITY;
    s[t] = v; __syncthreads();
    for (int off = 32; off > 0; off >>= 1) {
        if (t < off) s[t] = fmaxf(s[t], s[t + off]);
        __syncthreads();
    }
    float m = s[0]; __syncthreads();
    float e = (t < NC) ? expf(v - m) : 0.0f;
    s[t] = e; __syncthreads();
    for (int off = 32; off > 0; off >>= 1) {
        if (t < off) s[t] += s[t + off];
        __syncthreads();
    }
    float sum = s[0];
    if (t < NC) out[b * NC + t] = e / sum;
}

template <typename Sym>
static float* symaddr(const Sym& s) {
    void* p = nullptr;
    cudaGetSymbolAddress(&p, s);
    return (float*)p;
}

extern "C" void kernel_launch(void* const* d_in, const int* in_sizes, int n_in,
                              void* d_out, int out_size)
{
    const float* x   = (const float*)d_in[0];
    const float* Wx1 = (const float*)d_in[1];
    const float* Wh1 = (const float*)d_in[2];
    const float* b1  = (const float*)d_in[3];
    const float* Wx2 = (const float*)d_in[4];
    const float* Wh2 = (const float*)d_in[5];
    const float* b2  = (const float*)d_in[6];
    const float* Wx3 = (const float*)d_in[7];
    const float* Wh3 = (const float*)d_in[8];
    const float* b3  = (const float*)d_in[9];
    const float* Wx4 = (const float*)d_in[10];
    const float* Wh4 = (const float*)d_in[11];
    const float* b4  = (const float*)d_in[12];
    const float* Wd  = (const float*)d_in[13];
    const float* bd  = (const float*)d_in[14];
    float* out = (float*)d_out;

    float* hs1 = symaddr(g_hs1); float* c1 = symaddr(g_c1); float* p1 = symaddr(g_p1);
    float* hs2 = symaddr(g_hs2); float* c2 = symaddr(g_c2); float* p2 = symaddr(g_p2);
    float* hs3 = symaddr(g_hs3); float* c3 = symaddr(g_c3); float* p3 = symaddr(g_p3);
    float* hs4 = symaddr(g_hs4); float* c4 = symaddr(g_c4); float* p4 = symaddr(g_p4);
    float* logits = symaddr(g_logits);

    const int TB = 256;   // pool/aux kernels
    const int LB = 128;   // lstm_step block

    // ---- Layer 1: CIN=3, F=4, FT=4 (gy=1), PX=4, 128x128 -> 126x126 ----
    {
        constexpr int NTX = (126 + 3) / 4;                 // 32
        int nt = Bv * 126 * NTX;
        dim3 grid((nt + LB - 1) / LB, 1);
        for (int t = 0; t < Tv; t++)
            lstm_step<3, 4, 4, 128, 128, 4><<<grid, LB>>>(x, Wx1, Wh1, b1, hs1, c1, t);
        int total = Bv * Tv * 63 * 63 * 4;
        maxpool_k<<<(total + TB - 1) / TB, TB>>>(hs1, p1, 126, 126, 4, 63, 63, total);
    }
    // ---- Layer 2: CIN=4, F=8, FT=4 (gy=2), PX=4, 63x63 -> 61x61 ----
    {
        constexpr int NTX = (61 + 3) / 4;                  // 16
        int nt = Bv * 61 * NTX;
        dim3 grid((nt + LB - 1) / LB, 2);
        for (int t = 0; t < Tv; t++)
            lstm_step<4, 8, 4, 63, 63, 4><<<grid, LB>>>(p1, Wx2, Wh2, b2, hs2, c2, t);
        int total = Bv * Tv * 31 * 31 * 8;
        maxpool_k<<<(total + TB - 1) / TB, TB>>>(hs2, p2, 61, 61, 8, 31, 31, total);
    }
    // ---- Layer 3: CIN=8, F=12, FT=4 (gy=3), PX=4, 31x31 -> 29x29 ----
    {
        constexpr int NTX = (29 + 3) / 4;                  // 8
        int nt = Bv * 29 * NTX;
        dim3 grid((nt + LB - 1) / LB, 3);
        for (int t = 0; t < Tv; t++)
            lstm_step<8, 12, 4, 31, 31, 4><<<grid, LB>>>(p2, Wx3, Wh3, b3, hs3, c3, t);
        int total = Bv * Tv * 15 * 15 * 12;
        maxpool_k<<<(total + TB - 1) / TB, TB>>>(hs3, p3, 29, 29, 12, 15, 15, total);
    }
    // ---- Layer 4: CIN=12, F=16, FT=4 (gy=4), PX=2, 15x15 -> 13x13 ----
    {
        constexpr int NTX = (13 + 1) / 2;                  // 7
        int nt = Bv * 13 * NTX;
        dim3 grid((nt + LB - 1) / LB, 4);
        for (int t = 0; t < Tv; t++)
            lstm_step<12, 16, 4, 15, 15, 2><<<grid, LB>>>(p3, Wx4, Wh4, b4, hs4, c4, t);
        int total = Bv * Tv * 7 * 7 * 16;
        maxpool_k<<<(total + TB - 1) / TB, TB>>>(hs4, p4, 13, 13, 16, 7, 7, total);
    }

    // ---- Dense + softmax ----
    dim3 dgrid(Bv, 50);
    dense_k<<<dgrid, 128>>>(p4, Wd, bd, logits);
    softmax_k<<<Bv, 64>>>(logits, out);
}

// round 5
// speedup vs baseline: 1.4406x; 1.4406x over previous
#include <cuda_runtime.h>
#include <math.h>

// ---------------------------------------------------------------------------
// ConvLSTM stack, R3: planar-smem tiled step kernel.
// 4x (ConvLSTM2D(valid in-conv, same rec-conv, hsig gates i,f,c,o) + MaxPool2x2)
// -> Dense(50) -> softmax.  B=32, T=24, fp32.
// ---------------------------------------------------------------------------

static constexpr int Bv = 32;
static constexpr int Tv = 24;

__device__ float g_hs1[(size_t)Bv*Tv*126*126*4];
__device__ float g_c1 [(size_t)Bv*126*126*4];
__device__ float g_p1 [(size_t)Bv*Tv*63*63*4];
__device__ float g_hs2[(size_t)Bv*Tv*61*61*8];
__device__ float g_c2 [(size_t)Bv*61*61*8];
__device__ float g_p2 [(size_t)Bv*Tv*31*31*8];
__device__ float g_hs3[(size_t)Bv*Tv*29*29*12];
__device__ float g_c3 [(size_t)Bv*29*29*12];
__device__ float g_p3 [(size_t)Bv*Tv*15*15*12];
__device__ float g_hs4[(size_t)Bv*Tv*13*13*16];
__device__ float g_c4 [(size_t)Bv*13*13*16];
__device__ float g_p4 [(size_t)Bv*Tv*7*7*16];
__device__ float g_logits[Bv*50];

__device__ __forceinline__ float hsig(float x) { return __saturatef(0.2f * x + 0.5f); }

// Tiled ConvLSTM timestep. FT=4 gate channels per block (G4=16 gate values).
// Block = (TX, BY) threads; thread covers PY=TY/BY rows at (lx, ly + p*BY).
// Planar smem tiles: s_in[ci][y][x], s_h[ci][y][x] -> conflict-free LDS.
template<int CIN, int F, int HIN, int WIN, int TX, int TY, int BY>
__global__ void lstm_step_t(const float* __restrict__ in_seq,   // (B,T,HIN,WIN,CIN)
                            const float* __restrict__ Wx,       // (3,3,CIN,4F)
                            const float* __restrict__ Wh,       // (3,3,F,4F)
                            const float* __restrict__ bias,     // (4F,)
                            float* __restrict__ hs,             // (B,T,HO,WO,F)
                            float* __restrict__ c_buf,          // (B,HO,WO,F)
                            int t)
{
    constexpr int FT = 4, G4 = 16;
    constexpr int HO = HIN - 2, WO = WIN - 2;
    constexpr int C4 = 4 * F;
    constexpr int PY = TY / BY;
    constexpr int TXP = TX + 2, TYP = TY + 2;
    constexpr int NXT = (WO + TX - 1) / TX;
    constexpr int NYT = (HO + TY - 1) / TY;

    __shared__ float s_in[CIN * TYP * TXP];
    __shared__ float s_h [F   * TYP * TXP];
    __shared__ __align__(16) float s_wx[9 * CIN * G4];
    __shared__ __align__(16) float s_wh[9 * F   * G4];

    int bidx = blockIdx.x;
    const int xT = bidx % NXT; bidx /= NXT;
    const int yT = bidx % NYT; const int b = bidx / NYT;
    const int x0 = xT * TX, y0 = yT * TY;
    const int f0 = blockIdx.y * FT;
    const int lx = threadIdx.x, ly = threadIdx.y;
    const int tid = ly * TX + lx;
    constexpr int NTHR = TX * BY;

    // ---- weights (gate-column slice) into smem: [(tap*C+ci)][g*4+j] ----
    for (int i = tid; i < 9 * CIN * G4; i += NTHR) {
        int col = i & 15, rc = i >> 4;
        s_wx[i] = Wx[rc * C4 + (col >> 2) * F + f0 + (col & 3)];
    }
    for (int i = tid; i < 9 * F * G4; i += NTHR) {
        int col = i & 15, rc = i >> 4;
        s_wh[i] = Wh[rc * C4 + (col >> 2) * F + f0 + (col & 3)];
    }

    // ---- input tile (planar, zero-padded), rows y0..y0+TY+1, cols x0..x0+TX+1 ----
    {
        const float* xin = in_seq + ((size_t)(b * Tv + t)) * HIN * WIN * CIN;
        for (int i = tid; i < TYP * TXP * CIN; i += NTHR) {
            int ci = i % CIN; int r = i / CIN;
            int xx = r % TXP; int yy = r / TXP;
            int gy = y0 + yy, gx = x0 + xx;
            float v = (gy < HIN && gx < WIN) ? __ldg(&xin[((size_t)gy * WIN + gx) * CIN + ci]) : 0.0f;
            s_in[(ci * TYP + yy) * TXP + xx] = v;
        }
    }
    // ---- h_{t-1} tile (planar, zero-padded), rows y0-1.., cols x0-1.. ----
    if (t > 0) {
        const float* hp = hs + ((size_t)(b * Tv + (t - 1))) * HO * WO * F;
        for (int i = tid; i < TYP * TXP * F; i += NTHR) {
            int ci = i % F; int r = i / F;
            int xx = r % TXP; int yy = r / TXP;
            int hr = y0 - 1 + yy, hc = x0 - 1 + xx;
            float v = (hr >= 0 && hr < HO && hc >= 0 && hc < WO)
                        ? __ldg(&hp[((size_t)hr * WO + hc) * F + ci]) : 0.0f;
            s_h[(ci * TYP + yy) * TXP + xx] = v;
        }
    }
    __syncthreads();

    float acc[PY][G4];
    {
        float bv[G4];
        #pragma unroll
        for (int g = 0; g < 4; g++)
            #pragma unroll
            for (int j = 0; j < 4; j++)
                bv[g * 4 + j] = __ldg(&bias[g * F + f0 + j]);
        #pragma unroll
        for (int p = 0; p < PY; p++)
            #pragma unroll
            for (int k = 0; k < G4; k++) acc[p][k] = bv[k];
    }

    // ---- input conv (VALID) ----
    #pragma unroll
    for (int ky = 0; ky < 3; ky++) {
        #pragma unroll
        for (int kx = 0; kx < 3; kx++) {
            #pragma unroll
            for (int ci = 0; ci < CIN; ci++) {
                const float* wp = s_wx + ((ky * 3 + kx) * CIN + ci) * G4;
                float w[G4];
                #pragma unroll
                for (int q = 0; q < G4; q += 4) {
                    float4 t4 = *reinterpret_cast<const float4*>(wp + q);
                    w[q] = t4.x; w[q+1] = t4.y; w[q+2] = t4.z; w[q+3] = t4.w;
                }
                #pragma unroll
                for (int p = 0; p < PY; p++) {
                    float v = s_in[(ci * TYP + (ly + p * BY) + ky) * TXP + lx + kx];
                    #pragma unroll
                    for (int k = 0; k < G4; k++) acc[p][k] += v * w[k];
                }
            }
        }
    }

    // ---- recurrent conv (SAME) ----
    if (t > 0) {
        #pragma unroll
        for (int ky = 0; ky < 3; ky++) {
            #pragma unroll
            for (int kx = 0; kx < 3; kx++) {
                #pragma unroll
                for (int ci = 0; ci < F; ci++) {
                    const float* wp = s_wh + ((ky * 3 + kx) * F + ci) * G4;
                    float w[G4];
                    #pragma unroll
                    for (int q = 0; q < G4; q += 4) {
                        float4 t4 = *reinterpret_cast<const float4*>(wp + q);
                        w[q] = t4.x; w[q+1] = t4.y; w[q+2] = t4.z; w[q+3] = t4.w;
                    }
                    #pragma unroll
                    for (int p = 0; p < PY; p++) {
                        float v = s_h[(ci * TYP + (ly + p * BY) + ky) * TXP + lx + kx];
                        #pragma unroll
                        for (int k = 0; k < G4; k++) acc[p][k] += v * w[k];
                    }
                }
            }
        }
    }

    // ---- gates (i, f, c, o) + stores (float4) ----
    #pragma unroll
    for (int p = 0; p < PY; p++) {
        int gy = y0 + ly + p * BY;
        int gx = x0 + lx;
        if (gy >= HO || gx >= WO) continue;
        size_t pix = (size_t)b * HO * WO + (size_t)gy * WO + gx;
        float* cp = c_buf + pix * F + f0;
        float* ho = hs + ((size_t)(b * Tv + t)) * HO * WO * F + ((size_t)gy * WO + gx) * F + f0;
        float4 cold = (t > 0) ? *reinterpret_cast<const float4*>(cp)
                              : make_float4(0.f, 0.f, 0.f, 0.f);
        float co[4] = {cold.x, cold.y, cold.z, cold.w};
        float4 cn4, hn4;
        float cn[4], hn[4];
        #pragma unroll
        for (int j = 0; j < 4; j++) {
            float iv = acc[p][j];
            float fv = acc[p][4 + j];
            float cv = acc[p][8 + j];
            float ov = acc[p][12 + j];
            float c2 = hsig(fv) * co[j] + hsig(iv) * tanhf(cv);
            cn[j] = c2;
            hn[j] = hsig(ov) * tanhf(c2);
        }
        cn4 = make_float4(cn[0], cn[1], cn[2], cn[3]);
        hn4 = make_float4(hn[0], hn[1], hn[2], hn[3]);
        *reinterpret_cast<float4*>(cp) = cn4;
        *reinterpret_cast<float4*>(ho) = hn4;
    }
}

// MaxPool (1,2,2) stride (1,2,2), padding SAME, over (B*T, H, W, C)
__global__ void maxpool_k(const float* __restrict__ in, float* __restrict__ out,
                          int H, int W, int C, int HO, int WO, int total)
{
    int idx = blockIdx.x * blockDim.x + threadIdx.x;
    if (idx >= total) return;
    int c = idx % C; int r = idx / C;
    int ox = r % WO; r /= WO;
    int oy = r % HO; r /= HO;                 // r = bt
    const float* base = in + (size_t)r * H * W * C;
    int iy = 2 * oy, ix = 2 * ox;
    float m = base[((size_t)iy * W + ix) * C + c];
    if (ix + 1 < W) m = fmaxf(m, base[((size_t)iy * W + ix + 1) * C + c]);
    if (iy + 1 < H) {
        m = fmaxf(m, base[((size_t)(iy + 1) * W + ix) * C + c]);
        if (ix + 1 < W) m = fmaxf(m, base[((size_t)(iy + 1) * W + ix + 1) * C + c]);
    }
    out[idx] = m;
}

// Dense: logits[b,k] = sum_j xf[b,j]*Wd[j,k] + bd[k];   FLAT=18816, NC=50
__global__ void dense_k(const float* __restrict__ xf, const float* __restrict__ Wd,
                        const float* __restrict__ bd, float* __restrict__ logits)
{
    const int FLAT = 18816, NC = 50;
    int b = blockIdx.x, k = blockIdx.y;
    float s = 0.0f;
    for (int j = threadIdx.x; j < FLAT; j += blockDim.x)
        s += xf[(size_t)b * FLAT + j] * __ldg(&Wd[(size_t)j * NC + k]);
    __shared__ float red[128];
    red[threadIdx.x] = s;
    __syncthreads();
    for (int off = 64; off > 0; off >>= 1) {
        if (threadIdx.x < off) red[threadIdx.x] += red[threadIdx.x + off];
        __syncthreads();
    }
    if (threadIdx.x == 0) logits[b * NC + k] = red[0] + __ldg(&bd[k]);
}

__global__ void softmax_k(const float* __restrict__ logits, float* __restrict__ out)
{
    const int NC = 50;
    int b = blockIdx.x, t = threadIdx.x;
    __shared__ float s[64];
    float v = (t < NC) ? logits[b * NC + t] : -INFINITY;
    s[t] = v; __syncthreads();
    for (int off = 32; off > 0; off >>= 1) {
        if (t < off) s[t] = fmaxf(s[t], s[t + off]);
        __syncthreads();
    }
    float m = s[0]; __syncthreads();
    float e = (t < NC) ? expf(v - m) : 0.0f;
    s[t] = e; __syncthreads();
    for (int off = 32; off > 0; off >>= 1) {
        if (t < off) s[t] += s[t + off];
        __syncthreads();
    }
    float sum = s[0];
    if (t < NC) out[b * NC + t] = e / sum;
}

template <typename Sym>
static float* symaddr(const Sym& s) {
    void* p = nullptr;
    cudaGetSymbolAddress(&p, s);
    return (float*)p;
}

extern "C" void kernel_launch(void* const* d_in, const int* in_sizes, int n_in,
                              void* d_out, int out_size)
{
    const float* x   = (const float*)d_in[0];
    const float* Wx1 = (const float*)d_in[1];
    const float* Wh1 = (const float*)d_in[2];
    const float* b1  = (const float*)d_in[3];
    const float* Wx2 = (const float*)d_in[4];
    const float* Wh2 = (const float*)d_in[5];
    const float* b2  = (const float*)d_in[6];
    const float* Wx3 = (const float*)d_in[7];
    const float* Wh3 = (const float*)d_in[8];
    const float* b3  = (const float*)d_in[9];
    const float* Wx4 = (const float*)d_in[10];
    const float* Wh4 = (const float*)d_in[11];
    const float* b4  = (const float*)d_in[12];
    const float* Wd  = (const float*)d_in[13];
    const float* bd  = (const float*)d_in[14];
    float* out = (float*)d_out;

    float* hs1 = symaddr(g_hs1); float* c1 = symaddr(g_c1); float* p1 = symaddr(g_p1);
    float* hs2 = symaddr(g_hs2); float* c2 = symaddr(g_c2); float* p2 = symaddr(g_p2);
    float* hs3 = symaddr(g_hs3); float* c3 = symaddr(g_c3); float* p3 = symaddr(g_p3);
    float* hs4 = symaddr(g_hs4); float* c4 = symaddr(g_c4); float* p4 = symaddr(g_p4);
    float* logits = symaddr(g_logits);

    const int TB = 256;

    // ---- Layer 1: CIN=3,F=4, 128x128->126x126. TX=32,TY=16,BY=8 (PY=2), gy=1 ----
    {
        constexpr int NXT = (126 + 31) / 32, NYT = (126 + 15) / 16;   // 4, 8
        dim3 grid(Bv * NXT * NYT, 1), blk(32, 8);
        for (int t = 0; t < Tv; t++)
            lstm_step_t<3, 4, 128, 128, 32, 16, 8><<<grid, blk>>>(x, Wx1, Wh1, b1, hs1, c1, t);
        int total = Bv * Tv * 63 * 63 * 4;
        maxpool_k<<<(total + TB - 1) / TB, TB>>>(hs1, p1, 126, 126, 4, 63, 63, total);
    }
    // ---- Layer 2: CIN=4,F=8, 63x63->61x61. TX=32,TY=16,BY=8 (PY=2), gy=2 ----
    {
        constexpr int NXT = (61 + 31) / 32, NYT = (61 + 15) / 16;     // 2, 4
        dim3 grid(Bv * NXT * NYT, 2), blk(32, 8);
        for (int t = 0; t < Tv; t++)
            lstm_step_t<4, 8, 63, 63, 32, 16, 8><<<grid, blk>>>(p1, Wx2, Wh2, b2, hs2, c2, t);
        int total = Bv * Tv * 31 * 31 * 8;
        maxpool_k<<<(total + TB - 1) / TB, TB>>>(hs2, p2, 61, 61, 8, 31, 31, total);
    }
    // ---- Layer 3: CIN=8,F=12, 31x31->29x29. TX=32,TY=8,BY=8 (PY=1), gy=3 ----
    {
        constexpr int NXT = (29 + 31) / 32, NYT = (29 + 7) / 8;       // 1, 4
        dim3 grid(Bv * NXT * NYT, 3), blk(32, 8);
        for (int t = 0; t < Tv; t++)
            lstm_step_t<8, 12, 31, 31, 32, 8, 8><<<grid, blk>>>(p2, Wx3, Wh3, b3, hs3, c3, t);
        int total = Bv * Tv * 15 * 15 * 12;
        maxpool_k<<<(total + TB - 1) / TB, TB>>>(hs3, p3, 29, 29, 12, 15, 15, total);
    }
    // ---- Layer 4: CIN=12,F=16, 15x15->13x13. TX=16,TY=13,BY=13 (PY=1), gy=4 ----
    {
        dim3 grid(Bv, 4), blk(16, 13);
        for (int t = 0; t < Tv; t++)
            lstm_step_t<12, 16, 15, 15, 16, 13, 13><<<grid, blk>>>(p3, Wx4, Wh4, b4, hs4, c4, t);
        int total = Bv * Tv * 7 * 7 * 16;
        maxpool_k<<<(total + TB - 1) / TB, TB>>>(hs4, p4, 13, 13, 16, 7, 7, total);
    }

    // ---- Dense + softmax ----
    dim3 dgrid(Bv, 50);
    dense_k<<<dgrid, 128>>>(p4, Wd, bd, logits);
    softmax_k<<<Bv, 64>>>(logits, out);
}